// round 4
// baseline (speedup 1.0000x reference)
#include <cuda_runtime.h>
#include <math.h>
#include <stdint.h>

#define NQ 4096
#define NS 4096
#define D  1024
#define KC 128
#define EPSF 1e-12f
#define CH  32           // K chunk for GEMM mainloop

// ---------------- device scratch ----------------
__device__ float d_s2[NS];
__device__ float d_q2[NQ];
__device__ float d_selfdot[NQ];
__device__ int   d_cnt[KC];
__device__ float d_S2c[KC];
__device__ float d_mus[KC * D];
__device__ float d_mus2[KC];
__device__ float d_pn2[KC];
__device__ float d_invc[KC];
__device__ float d_perq[NQ];

// ---------------- helpers ----------------
__device__ __forceinline__ float wsum(float v) {
#pragma unroll
    for (int o = 16; o; o >>= 1) v += __shfl_xor_sync(0xffffffffu, v, o);
    return v;
}
__device__ __forceinline__ float wmax(float v) {
#pragma unroll
    for (int o = 16; o; o >>= 1) v = fmaxf(v, __shfl_xor_sync(0xffffffffu, v, o));
    return v;
}
__device__ __forceinline__ uint32_t f2tf32(float f) {
    uint32_t r;
    asm("cvt.rna.tf32.f32 %0, %1;" : "=r"(r) : "f"(f));
    return r;
}

// ---------------- K1: per-row norms + self dot (warp-per-row) -------------
__global__ __launch_bounds__(256) void k_norms(const float* __restrict__ xq,
                                               const float* __restrict__ xs,
                                               const int* __restrict__ pos) {
    int i = blockIdx.x * 8 + (threadIdx.x >> 5);
    int ln = threadIdx.x & 31;
    int p = __ldg(pos + i);
    const float4* xr = (const float4*)(xs + (size_t)i * D);
    const float4* qr = (const float4*)(xq + (size_t)i * D);
    const float4* pr = (const float4*)(xs + (size_t)p * D);
    float s2 = 0.f, q2 = 0.f, sd = 0.f;
#pragma unroll
    for (int l = 0; l < 8; l++) {
        int idx = ln + 32 * l;
        float4 a = xr[idx];
        s2 += a.x * a.x + a.y * a.y + a.z * a.z + a.w * a.w;
        float4 q = qr[idx];
        q2 += q.x * q.x + q.y * q.y + q.z * q.z + q.w * q.w;
        float4 b = pr[idx];
        sd += q.x * b.x + q.y * b.y + q.z * b.z + q.w * b.w;
    }
    s2 = wsum(s2); q2 = wsum(q2); sd = wsum(sd);
    if (ln == 0) {
        d_s2[i] = s2;
        d_q2[i] = q2;
        d_selfdot[i] = sd;
    }
}

// ---------------- K2: fused per-class stats + feature sums ----------------
__global__ __launch_bounds__(256) void k_mus(const float* __restrict__ xs,
                                             const int* __restrict__ ys) {
    int c = blockIdx.x, t = threadIdx.x;
    __shared__ int rows[NS];
    __shared__ int sc[256];
    __shared__ float red[256];

    int myy[16];
    int j0 = t * 16;
#pragma unroll
    for (int j = 0; j < 16; j++) myy[j] = ys[j0 + j];
    int count = 0;
#pragma unroll
    for (int j = 0; j < 16; j++) count += (myy[j] == c);

    sc[t] = count;
    __syncthreads();
    for (int o = 1; o < 256; o <<= 1) {
        int v = (t >= o) ? sc[t - o] : 0;
        __syncthreads();
        sc[t] += v;
        __syncthreads();
    }
    int off = sc[t] - count;
    int cnt = sc[255];
#pragma unroll
    for (int j = 0; j < 16; j++) {
        if (myy[j] == c) rows[off++] = j0 + j;
    }
    __syncthreads();

    float4 acc = make_float4(0.f, 0.f, 0.f, 0.f);
    for (int r = 0; r < cnt; r++) {
        float4 v = ((const float4*)(xs + (size_t)rows[r] * D))[t];
        acc.x += v.x; acc.y += v.y; acc.z += v.z; acc.w += v.w;
    }
    ((float4*)(d_mus + (size_t)c * D))[t] = acc;

    red[t] = acc.x * acc.x + acc.y * acc.y + acc.z * acc.z + acc.w * acc.w;
    __syncthreads();
    for (int s = 128; s; s >>= 1) {
        if (t < s) red[t] += red[t + s];
        __syncthreads();
    }

    if (t < 32) {
        float s = 0.f;
        for (int r = t; r < cnt; r += 32) s += d_s2[rows[r]];
        s = wsum(s);
        if (t == 0) {
            d_S2c[c] = s;
            d_cnt[c] = cnt;
            float m2 = red[0];
            d_mus2[c] = m2;
            float cc = fmaxf((float)cnt, 0.1f);
            d_invc[c] = 1.f / cc;
            d_pn2[c] = m2 / (cc * cc);
        }
    }
}

// ---------------- K3: fused dots GEMM + finalize --------------------------
// grid NQ/32, block 256. Tile M=32 (queries), N=128 (all classes), K=1024.
// 8 warps: 2 (M) x 4 (N); warp tile m16 x n32 of m16n8k8 tf32 mma.
// Epilogue: stage 32x128 dots in smem, warp w finalizes queries 4w..4w+3.
__global__ __launch_bounds__(256) void k_dots_fin(const float* __restrict__ xq,
                                                  const int* __restrict__ yq,
                                                  const int* __restrict__ ys,
                                                  const int* __restrict__ pos) {
    __shared__ uint32_t As[32][36];
    __shared__ uint32_t Bs[128][36];
    __shared__ float sd[32][132];

    int qb = blockIdx.x * 32;
    int t = threadIdx.x;
    int lane = t & 31, wid = t >> 5;
    int wm = (wid >> 2) * 16;     // 0 or 16
    int wn = (wid & 3) * 32;      // 0,32,64,96
    int g = lane >> 2, ci = lane & 3;

    // A load map: thread t -> row t>>3 (0..31), col0 (t&7)*4  (1 float4)
    int arow = t >> 3, acol = (t & 7) * 4;
    // B load map: thread t -> row t>>1 (0..127), col0 (t&1)*16 (4 float4)
    int brow = t >> 1, bcol = (t & 1) * 16;

    float acc[4][4];
#pragma unroll
    for (int b = 0; b < 4; b++)
#pragma unroll
        for (int r = 0; r < 4; r++) acc[b][r] = 0.f;

    const float* Aptr = xq + (size_t)(qb + arow) * D + acol;
    const float* Bptr = d_mus + (size_t)brow * D + bcol;

    float4 aR;
    float4 bR[4];
    aR = *(const float4*)Aptr;
#pragma unroll
    for (int i = 0; i < 4; i++) bR[i] = ((const float4*)Bptr)[i];

    for (int ch = 0; ch < D / CH; ch++) {
        __syncthreads();
        {
            uint4 ua;
            ua.x = f2tf32(aR.x); ua.y = f2tf32(aR.y);
            ua.z = f2tf32(aR.z); ua.w = f2tf32(aR.w);
            *(uint4*)&As[arow][acol] = ua;
#pragma unroll
            for (int i = 0; i < 4; i++) {
                uint4 ub;
                ub.x = f2tf32(bR[i].x); ub.y = f2tf32(bR[i].y);
                ub.z = f2tf32(bR[i].z); ub.w = f2tf32(bR[i].w);
                *(uint4*)&Bs[brow][bcol + 4 * i] = ub;
            }
        }
        __syncthreads();
        if (ch + 1 < D / CH) {
            aR = *(const float4*)(Aptr + (ch + 1) * CH);
            const float* Bn = Bptr + (ch + 1) * CH;
#pragma unroll
            for (int i = 0; i < 4; i++) bR[i] = ((const float4*)Bn)[i];
        }
#pragma unroll
        for (int k0 = 0; k0 < CH; k0 += 8) {
            uint32_t af[4], bf[4][2];
            af[0] = As[wm + g][k0 + ci];
            af[1] = As[wm + g + 8][k0 + ci];
            af[2] = As[wm + g][k0 + ci + 4];
            af[3] = As[wm + g + 8][k0 + ci + 4];
#pragma unroll
            for (int nt = 0; nt < 4; nt++) {
                int r = wn + nt * 8 + g;
                bf[nt][0] = Bs[r][k0 + ci];
                bf[nt][1] = Bs[r][k0 + ci + 4];
            }
#pragma unroll
            for (int nt = 0; nt < 4; nt++) {
                asm volatile(
                    "mma.sync.aligned.m16n8k8.row.col.f32.tf32.tf32.f32 "
                    "{%0,%1,%2,%3}, {%4,%5,%6,%7}, {%8,%9}, {%0,%1,%2,%3};\n"
                    : "+f"(acc[nt][0]), "+f"(acc[nt][1]),
                      "+f"(acc[nt][2]), "+f"(acc[nt][3])
                    : "r"(af[0]), "r"(af[1]), "r"(af[2]), "r"(af[3]),
                      "r"(bf[nt][0]), "r"(bf[nt][1]));
            }
        }
    }

    // stage dots in smem
    __syncthreads();
#pragma unroll
    for (int nt = 0; nt < 4; nt++) {
        int col = wn + nt * 8 + 2 * ci;
        sd[wm + g][col]     = acc[nt][0];
        sd[wm + g][col + 1] = acc[nt][1];
        sd[wm + g + 8][col]     = acc[nt][2];
        sd[wm + g + 8][col + 1] = acc[nt][3];
    }
    __syncthreads();

    // finalize: warp wid handles rows 4*wid .. 4*wid+3
#pragma unroll
    for (int rr = 0; rr < 4; rr++) {
        int r = wid * 4 + rr;
        int i = qb + r;
        float q2 = d_q2[i];
        int p = __ldg(pos + i);
        int cnew = __ldg(ys + p);
        int cq = __ldg(yq + i);

        float logit[4];
        float lmax = -1e30f;
        float dotq_c = 0.f;
#pragma unroll
        for (int kk = 0; kk < 4; kk++) {
            int k = lane + 32 * kk;
            float dot = sd[r][k];
            if (k == cq) dotq_c = dot;
            float lg;
            if (k == cnew) {
                float Cc = fmaxf((float)d_cnt[cnew] - 1.f, 0.1f);
                float qp = (dot - q2) / Cc;
                float pp2 = (d_mus2[cnew] - 2.f * dot + q2) / (Cc * Cc);
                float dp2 = q2 - 2.f * qp + pp2;
                lg = -sqrtf(fmaxf(dp2, 0.f) + EPSF);
            } else {
                float d2 = fmaxf(q2 + d_pn2[k] - 2.f * dot * d_invc[k], 0.f);
                lg = -sqrtf(d2 + EPSF);
            }
            logit[kk] = lg;
            lmax = fmaxf(lmax, lg);
        }
        float mall = wmax(lmax);
        float e = 0.f;
#pragma unroll
        for (int kk = 0; kk < 4; kk++) e += expf(logit[kk] - mall);
        float tot = wsum(e);
        float dotq = wsum(dotq_c);

        if (lane == 0) {
            float neg = mall + logf(tot);
            int cntq = d_cnt[cq];
            float sumd2 = (float)cntq * q2 + d_S2c[cq] - 2.f * dotq;
            bool cmpos = (cq == cnew);
            bool idxf = cntq > 1;
            float numer = sumd2;
            float denom = (float)cntq;
            if (cmpos) {
                float d2self = fmaxf(q2 + d_s2[p] - 2.f * d_selfdot[i], 0.f);
                numer -= d2self;
                denom -= 1.f;
                if (!idxf) denom += 1.f;
            }
            float poslog = (denom > 0.f) ? (-0.5f * numer / denom) : 0.f;
            d_perq[i] = neg - poslog;
        }
    }
}

// ---------------- K4: deterministic final mean ----------------------------
__global__ void k_loss(float* __restrict__ out) {
    int t = threadIdx.x;
    __shared__ float sh[1024];
    float v = d_perq[t] + d_perq[t + 1024] + d_perq[t + 2048] + d_perq[t + 3072];
    sh[t] = v;
    __syncthreads();
    for (int s = 512; s; s >>= 1) {
        if (t < s) sh[t] += sh[t + s];
        __syncthreads();
    }
    if (t == 0) out[0] = sh[0] * (1.f / (float)NQ);
}

// --------------------------------------------------------------------------
extern "C" void kernel_launch(void* const* d_in, const int* in_sizes, int n_in,
                              void* d_out, int out_size) {
    const float* xq  = (const float*)d_in[0];
    const int*   yq  = (const int*)d_in[1];
    const float* xs  = (const float*)d_in[2];
    const int*   ys  = (const int*)d_in[3];
    const int*   pos = (const int*)d_in[4];
    float* out = (float*)d_out;

    k_norms<<<NQ / 8, 256>>>(xq, xs, pos);
    k_mus<<<KC, 256>>>(xs, ys);
    k_dots_fin<<<NQ / 32, 256>>>(xq, yq, ys, pos);
    k_loss<<<1, 1024>>>(out);
}

// round 5
// speedup vs baseline: 1.2114x; 1.2114x over previous
#include <cuda_runtime.h>
#include <math.h>
#include <stdint.h>

#define NQ 4096
#define NS 4096
#define D  1024
#define KC 128
#define EPSF 1e-12f
#define KSP 4            // split-K for dots GEMM
#define KPB (D / KSP)    // 256 K per split
#define CH  32           // K chunk
#define NFB (NQ / 8)     // finalize blocks = 512

// ---------------- device scratch ----------------
__device__ float d_q2[NQ];
__device__ float d_d2self[NQ];
__device__ int   d_cnt[KC];
__device__ float d_S2c[KC];
__device__ float d_mus[KC * D];
__device__ float d_mus2[KC];
__device__ float d_pn2[KC];
__device__ float d_invc[KC];
__device__ float d_dotsp[NQ * KC * KSP];   // [i][k][s] split partials
__device__ float d_psum[NFB];

// ---------------- helpers ----------------
__device__ __forceinline__ float wsum(float v) {
#pragma unroll
    for (int o = 16; o; o >>= 1) v += __shfl_xor_sync(0xffffffffu, v, o);
    return v;
}
__device__ __forceinline__ float wmax(float v) {
#pragma unroll
    for (int o = 16; o; o >>= 1) v = fmaxf(v, __shfl_xor_sync(0xffffffffu, v, o));
    return v;
}
__device__ __forceinline__ uint32_t f2tf32(float f) {
    uint32_t r;
    asm("cvt.rna.tf32.f32 %0, %1;" : "=r"(r) : "f"(f));
    return r;
}

// ---------------- K1: q2 + self distance (warp-per-query) -----------------
// grid NQ/8, block 256. q2[i] = |xq_i|^2 ; d2self[i] = |xq_i - xs_{pos_i}|^2
__global__ __launch_bounds__(256) void k_norms(const float* __restrict__ xq,
                                               const float* __restrict__ xs,
                                               const int* __restrict__ pos) {
    int i = blockIdx.x * 8 + (threadIdx.x >> 5);
    int ln = threadIdx.x & 31;
    int p = __ldg(pos + i);
    const float4* qr = (const float4*)(xq + (size_t)i * D);
    const float4* pr = (const float4*)(xs + (size_t)p * D);
    float q2 = 0.f, ds = 0.f;
#pragma unroll
    for (int l = 0; l < 8; l++) {
        int idx = ln + 32 * l;
        float4 q = qr[idx];
        q2 += q.x * q.x + q.y * q.y + q.z * q.z + q.w * q.w;
        float4 b = pr[idx];
        float dx = q.x - b.x, dy = q.y - b.y, dz = q.z - b.z, dw = q.w - b.w;
        ds += dx * dx + dy * dy + dz * dz + dw * dw;
    }
    q2 = wsum(q2); ds = wsum(ds);
    if (ln == 0) {
        d_q2[i] = q2;
        d_d2self[i] = ds;
    }
}

// ---------------- K2: fused per-class stats + feature sums ----------------
// grid KC, block 256. Also computes S2c directly from the class rows.
__global__ __launch_bounds__(256) void k_mus(const float* __restrict__ xs,
                                             const int* __restrict__ ys) {
    int c = blockIdx.x, t = threadIdx.x;
    __shared__ int rows[NS];
    __shared__ int sc[256];
    __shared__ float red[256];

    int myy[16];
    int j0 = t * 16;
#pragma unroll
    for (int j = 0; j < 16; j++) myy[j] = ys[j0 + j];
    int count = 0;
#pragma unroll
    for (int j = 0; j < 16; j++) count += (myy[j] == c);

    sc[t] = count;
    __syncthreads();
    for (int o = 1; o < 256; o <<= 1) {
        int v = (t >= o) ? sc[t - o] : 0;
        __syncthreads();
        sc[t] += v;
        __syncthreads();
    }
    int off = sc[t] - count;
    int cnt = sc[255];
#pragma unroll
    for (int j = 0; j < 16; j++) {
        if (myy[j] == c) rows[off++] = j0 + j;
    }
    __syncthreads();

    float4 acc = make_float4(0.f, 0.f, 0.f, 0.f);
    float sq = 0.f;   // sum over class rows of x^2 on this thread's dims
    for (int r = 0; r < cnt; r++) {
        float4 v = ((const float4*)(xs + (size_t)rows[r] * D))[t];
        acc.x += v.x; acc.y += v.y; acc.z += v.z; acc.w += v.w;
        sq += v.x * v.x + v.y * v.y + v.z * v.z + v.w * v.w;
    }
    ((float4*)(d_mus + (size_t)c * D))[t] = acc;

    // reduction 1: |mus|^2
    red[t] = acc.x * acc.x + acc.y * acc.y + acc.z * acc.z + acc.w * acc.w;
    __syncthreads();
    for (int s = 128; s; s >>= 1) {
        if (t < s) red[t] += red[t + s];
        __syncthreads();
    }
    float m2 = red[0];
    __syncthreads();
    // reduction 2: S2c
    red[t] = sq;
    __syncthreads();
    for (int s = 128; s; s >>= 1) {
        if (t < s) red[t] += red[t + s];
        __syncthreads();
    }
    if (t == 0) {
        d_S2c[c] = red[0];
        d_cnt[c] = cnt;
        d_mus2[c] = m2;
        float cc = fmaxf((float)cnt, 0.1f);
        d_invc[c] = 1.f / cc;
        d_pn2[c] = m2 / (cc * cc);
    }
}

// ---------------- K3: dots = XQ @ MUS^T via tf32 mma.sync -----------------
// grid (NQ/128, KSP), block 256 (8 warps, 2Mx4N). Block tile 128x128.
__global__ __launch_bounds__(256) void k_dots(const float* __restrict__ xq) {
    __shared__ uint32_t As[128][36];
    __shared__ uint32_t Bs[128][36];

    int qb = blockIdx.x * 128;
    int sp = blockIdx.y;
    int t = threadIdx.x;
    int lane = t & 31, wid = t >> 5;
    int wm = (wid >> 2) * 64;
    int wn = (wid & 3) * 32;
    int g = lane >> 2, ci = lane & 3;

    int lrow = t >> 1;
    int lcol0 = (t & 1) * 16;

    float acc[4][4][4];
#pragma unroll
    for (int a = 0; a < 4; a++)
#pragma unroll
        for (int b = 0; b < 4; b++)
#pragma unroll
            for (int r = 0; r < 4; r++) acc[a][b][r] = 0.f;

    const float* Aptr = xq + (size_t)(qb + lrow) * D + sp * KPB + lcol0;
    const float* Bptr = d_mus + (size_t)lrow * D + sp * KPB + lcol0;

    float4 aR[4], bR[4];
#pragma unroll
    for (int i = 0; i < 4; i++) {
        aR[i] = ((const float4*)Aptr)[i];
        bR[i] = ((const float4*)Bptr)[i];
    }

    for (int ch = 0; ch < KPB / CH; ch++) {
        __syncthreads();
#pragma unroll
        for (int i = 0; i < 4; i++) {
            uint4 ua, ub;
            ua.x = f2tf32(aR[i].x); ua.y = f2tf32(aR[i].y);
            ua.z = f2tf32(aR[i].z); ua.w = f2tf32(aR[i].w);
            ub.x = f2tf32(bR[i].x); ub.y = f2tf32(bR[i].y);
            ub.z = f2tf32(bR[i].z); ub.w = f2tf32(bR[i].w);
            *(uint4*)&As[lrow][lcol0 + 4 * i] = ua;
            *(uint4*)&Bs[lrow][lcol0 + 4 * i] = ub;
        }
        __syncthreads();
        if (ch + 1 < KPB / CH) {
            const float* An = Aptr + (ch + 1) * CH;
            const float* Bn = Bptr + (ch + 1) * CH;
#pragma unroll
            for (int i = 0; i < 4; i++) {
                aR[i] = ((const float4*)An)[i];
                bR[i] = ((const float4*)Bn)[i];
            }
        }
#pragma unroll
        for (int k0 = 0; k0 < CH; k0 += 8) {
            uint32_t af[4][4], bf[4][2];
#pragma unroll
            for (int mt = 0; mt < 4; mt++) {
                int r = wm + mt * 16 + g;
                af[mt][0] = As[r][k0 + ci];
                af[mt][1] = As[r + 8][k0 + ci];
                af[mt][2] = As[r][k0 + ci + 4];
                af[mt][3] = As[r + 8][k0 + ci + 4];
            }
#pragma unroll
            for (int nt = 0; nt < 4; nt++) {
                int r = wn + nt * 8 + g;
                bf[nt][0] = Bs[r][k0 + ci];
                bf[nt][1] = Bs[r][k0 + ci + 4];
            }
#pragma unroll
            for (int mt = 0; mt < 4; mt++)
#pragma unroll
                for (int nt = 0; nt < 4; nt++) {
                    asm volatile(
                        "mma.sync.aligned.m16n8k8.row.col.f32.tf32.tf32.f32 "
                        "{%0,%1,%2,%3}, {%4,%5,%6,%7}, {%8,%9}, {%0,%1,%2,%3};\n"
                        : "+f"(acc[mt][nt][0]), "+f"(acc[mt][nt][1]),
                          "+f"(acc[mt][nt][2]), "+f"(acc[mt][nt][3])
                        : "r"(af[mt][0]), "r"(af[mt][1]), "r"(af[mt][2]), "r"(af[mt][3]),
                          "r"(bf[nt][0]), "r"(bf[nt][1]));
                }
        }
    }

    // epilogue: [i][k][s] layout so finalize reads one float4 per class
#pragma unroll
    for (int mt = 0; mt < 4; mt++)
#pragma unroll
        for (int nt = 0; nt < 4; nt++) {
            int row = qb + wm + mt * 16 + g;
            int col = wn + nt * 8 + 2 * ci;
            d_dotsp[((size_t)row * KC + col) * KSP + sp]           = acc[mt][nt][0];
            d_dotsp[((size_t)row * KC + col + 1) * KSP + sp]       = acc[mt][nt][1];
            d_dotsp[((size_t)(row + 8) * KC + col) * KSP + sp]     = acc[mt][nt][2];
            d_dotsp[((size_t)(row + 8) * KC + col + 1) * KSP + sp] = acc[mt][nt][3];
        }
}

// ---------------- K4: finalize, warp-per-query ---------------------------
// grid NQ/8, block 256. Warp handles query i; per-block partial sum out.
__global__ __launch_bounds__(256) void k_finalize(const int* __restrict__ yq,
                                                  const int* __restrict__ ys,
                                                  const int* __restrict__ pos) {
    int wid = threadIdx.x >> 5;
    int i = blockIdx.x * 8 + wid;
    int ln = threadIdx.x & 31;
    float q2 = d_q2[i];
    int p = __ldg(pos + i);
    int cnew = __ldg(ys + p);
    int cq = __ldg(yq + i);

    float logit[4];
    float lmax = -1e30f;
    float dotq_c = 0.f;
#pragma unroll
    for (int kk = 0; kk < 4; kk++) {
        int k = ln + 32 * kk;
        float4 ld = *(const float4*)(d_dotsp + ((size_t)i * KC + k) * KSP);
        float dot = (ld.x + ld.y) + (ld.z + ld.w);
        if (k == cq) dotq_c = dot;
        float lg;
        if (k == cnew) {
            float Cc = fmaxf((float)d_cnt[cnew] - 1.f, 0.1f);
            float qp = (dot - q2) / Cc;
            float pp2 = (d_mus2[cnew] - 2.f * dot + q2) / (Cc * Cc);
            float dp2 = q2 - 2.f * qp + pp2;
            lg = -sqrtf(fmaxf(dp2, 0.f) + EPSF);
        } else {
            float d2 = fmaxf(q2 + d_pn2[k] - 2.f * dot * d_invc[k], 0.f);
            lg = -sqrtf(d2 + EPSF);
        }
        logit[kk] = lg;
        lmax = fmaxf(lmax, lg);
    }
    float mall = wmax(lmax);
    float e = 0.f;
#pragma unroll
    for (int kk = 0; kk < 4; kk++) e += expf(logit[kk] - mall);
    float tot = wsum(e);
    float dotq = wsum(dotq_c);

    __shared__ float sh[8];
    if (ln == 0) {
        float neg = mall + logf(tot);
        int cntq = d_cnt[cq];
        float sumd2 = (float)cntq * q2 + d_S2c[cq] - 2.f * dotq;
        bool cmpos = (cq == cnew);
        bool idxf = cntq > 1;
        float numer = sumd2;
        float denom = (float)cntq;
        if (cmpos) {
            numer -= fmaxf(d_d2self[i], 0.f);
            denom -= 1.f;
            if (!idxf) denom += 1.f;
        }
        float poslog = (denom > 0.f) ? (-0.5f * numer / denom) : 0.f;
        sh[wid] = neg - poslog;
    }
    __syncthreads();
    if (threadIdx.x == 0) {
        float s = 0.f;
#pragma unroll
        for (int w = 0; w < 8; w++) s += sh[w];
        d_psum[blockIdx.x] = s;
    }
}

// ---------------- K5: final mean over 512 block partials ------------------
__global__ void k_loss(float* __restrict__ out) {
    int t = threadIdx.x;
    __shared__ float sh[NFB];
    sh[t] = d_psum[t];
    __syncthreads();
    for (int s = NFB / 2; s; s >>= 1) {
        if (t < s) sh[t] += sh[t + s];
        __syncthreads();
    }
    if (t == 0) out[0] = sh[0] * (1.f / (float)NQ);
}

// --------------------------------------------------------------------------
extern "C" void kernel_launch(void* const* d_in, const int* in_sizes, int n_in,
                              void* d_out, int out_size) {
    const float* xq  = (const float*)d_in[0];
    const int*   yq  = (const int*)d_in[1];
    const float* xs  = (const float*)d_in[2];
    const int*   ys  = (const int*)d_in[3];
    const int*   pos = (const int*)d_in[4];
    float* out = (float*)d_out;

    k_mus<<<KC, 256>>>(xs, ys);
    k_norms<<<NQ / 8, 256>>>(xq, xs, pos);
    k_dots<<<dim3(NQ / 128, KSP), 256>>>(xq);
    k_finalize<<<NQ / 8, 256>>>(yq, ys, pos);
    k_loss<<<1, NFB>>>(out);
}